// round 7
// baseline (speedup 1.0000x reference)
#include <cuda_runtime.h>
#include <cstdint>

// Problem constants: G=512, GP=256, keys fit in 24 bits since b==0.
#define NKEYS  (1u << 24)          // 16,777,216 possible parent keys
#define NWORDS (1u << 19)          // bitmap words (32 keys/word)
#define NBLKS  (NWORDS / 1024)     // 512 scan blocks
#define NMAX   4000000
#define NCHUNK 256                 // partition chunks (blocks in build/partition)
#define NBUCK  4096                // buckets = key >> 12
#define KPB    4096                // keys per bucket
#define WPB    (KPB / 32)          // bitmap words per bucket = 128

// Scratch (static device globals)
__device__ unsigned g_bitmap[NWORDS];
__device__ unsigned g_wprefix[NWORDS];       // per-word excl popcount prefix (within 1024-word block)
__device__ unsigned g_blocksums[NBLKS];      // 1024-word block excl prefix
__device__ unsigned g_total;                 // number of unique keys
__device__ unsigned g_combined[NMAX];        // (key<<3)|offset per point
__device__ unsigned g_hist[NCHUNK * NBUCK];  // [chunk][bucket] counts -> per-bucket chunk prefix
__device__ unsigned g_btotal[NBUCK];         // per-bucket totals
__device__ unsigned g_bprefix[NBUCK];        // exclusive bucket prefix
__device__ uint2    g_bucket[NMAX];          // {combined, feat bits} grouped by bucket

__global__ void k_zero_bitmap() {
    unsigned i = blockIdx.x * blockDim.x + threadIdx.x;
    if (i < NWORDS / 4) reinterpret_cast<uint4*>(g_bitmap)[i] = make_uint4(0, 0, 0, 0);
}

// ---------------------------------------------------------------------------
// Pass 1: key+offset, presence bit, per-chunk bucket histogram.
// ---------------------------------------------------------------------------
__global__ __launch_bounds__(1024) void k_build(const int4* __restrict__ coords, int n, int chunk) {
    __shared__ unsigned hist[NBUCK];
    for (int i = threadIdx.x; i < NBUCK; i += 1024) hist[i] = 0;
    __syncthreads();
    int c = blockIdx.x;
    int lo = c * chunk;
    int hi = min(n, lo + chunk);
    for (int i = lo + threadIdx.x; i < hi; i += 1024) {
        int4 cc = coords[i];
        unsigned key = (((unsigned)cc.x * 256u + (((unsigned)cc.y) >> 1)) * 256u
                        + (((unsigned)cc.z) >> 1)) * 256u + (((unsigned)cc.w) >> 1);
        unsigned off = (((unsigned)cc.y & 1u) << 2) | (((unsigned)cc.z & 1u) << 1)
                     | ((unsigned)cc.w & 1u);
        g_combined[i] = (key << 3) | off;
        atomicOr(&g_bitmap[key >> 5], 1u << (key & 31u));
        atomicAdd(&hist[key >> 12], 1u);
    }
    __syncthreads();
    for (int i = threadIdx.x; i < NBUCK; i += 1024) g_hist[c * NBUCK + i] = hist[i];
}

// ---------------------------------------------------------------------------
// Pass 2a: per-1024-word-block exclusive scan of bitmap popcounts.
// ---------------------------------------------------------------------------
__global__ void k_scan_words() {
    __shared__ unsigned warp_sums[32];
    unsigned w = blockIdx.x * 1024u + threadIdx.x;
    unsigned c = __popc(g_bitmap[w]);
    unsigned v = c;
    #pragma unroll
    for (int d = 1; d < 32; d <<= 1) {
        unsigned t = __shfl_up_sync(0xFFFFFFFFu, v, d);
        if ((threadIdx.x & 31u) >= (unsigned)d) v += t;
    }
    if ((threadIdx.x & 31u) == 31u) warp_sums[threadIdx.x >> 5] = v;
    __syncthreads();
    if (threadIdx.x < 32) {
        unsigned s = warp_sums[threadIdx.x];
        #pragma unroll
        for (int d = 1; d < 32; d <<= 1) {
            unsigned t = __shfl_up_sync(0xFFFFFFFFu, s, d);
            if (threadIdx.x >= (unsigned)d) s += t;
        }
        warp_sums[threadIdx.x] = s;
    }
    __syncthreads();
    unsigned warp_off = (threadIdx.x >= 32) ? warp_sums[(threadIdx.x >> 5) - 1] : 0u;
    g_wprefix[w] = warp_off + v - c;
    if (threadIdx.x == 1023) g_blocksums[blockIdx.x] = warp_off + v;
}

// ---------------------------------------------------------------------------
// Pass 2b: exclusive scan of 512 block totals; publish g_total.
// ---------------------------------------------------------------------------
__global__ void k_scan_blocks() {
    __shared__ unsigned warp_sums[16];
    unsigned c = g_blocksums[threadIdx.x];
    unsigned v = c;
    #pragma unroll
    for (int d = 1; d < 32; d <<= 1) {
        unsigned t = __shfl_up_sync(0xFFFFFFFFu, v, d);
        if ((threadIdx.x & 31u) >= (unsigned)d) v += t;
    }
    if ((threadIdx.x & 31u) == 31u) warp_sums[threadIdx.x >> 5] = v;
    __syncthreads();
    if (threadIdx.x < 16) {
        unsigned s = warp_sums[threadIdx.x];
        #pragma unroll
        for (int d = 1; d < 16; d <<= 1) {
            unsigned t = __shfl_up_sync(0xFFFFu, s, d);
            if (threadIdx.x >= (unsigned)d) s += t;
        }
        warp_sums[threadIdx.x] = s;
    }
    __syncthreads();
    unsigned warp_off = (threadIdx.x >= 32) ? warp_sums[(threadIdx.x >> 5) - 1] : 0u;
    g_blocksums[threadIdx.x] = warp_off + v - c;
    if (threadIdx.x == NBLKS - 1) g_total = warp_off + v;
}

// ---------------------------------------------------------------------------
// Pass 2c: per-bucket running prefix across chunks (in place) + bucket totals.
// ---------------------------------------------------------------------------
__global__ void k_chunkpref() {
    int b = blockIdx.x * blockDim.x + threadIdx.x;   // 4096 threads
    if (b >= NBUCK) return;
    unsigned run = 0;
    for (int c = 0; c < NCHUNK; c++) {
        unsigned t = g_hist[c * NBUCK + b];
        g_hist[c * NBUCK + b] = run;
        run += t;
    }
    g_btotal[b] = run;
}

// ---------------------------------------------------------------------------
// Pass 2d: exclusive scan of 4096 bucket totals (1 block, 4 per thread).
// ---------------------------------------------------------------------------
__global__ __launch_bounds__(1024) void k_bucket_prefix() {
    __shared__ unsigned warp_sums[32];
    int t = threadIdx.x;
    unsigned v0 = g_btotal[t * 4 + 0];
    unsigned v1 = g_btotal[t * 4 + 1];
    unsigned v2 = g_btotal[t * 4 + 2];
    unsigned v3 = g_btotal[t * 4 + 3];
    unsigned sum = v0 + v1 + v2 + v3;
    unsigned v = sum;
    #pragma unroll
    for (int d = 1; d < 32; d <<= 1) {
        unsigned x = __shfl_up_sync(0xFFFFFFFFu, v, d);
        if ((t & 31) >= d) v += x;
    }
    if ((t & 31) == 31) warp_sums[t >> 5] = v;
    __syncthreads();
    if (t < 32) {
        unsigned s = warp_sums[t];
        #pragma unroll
        for (int d = 1; d < 32; d <<= 1) {
            unsigned x = __shfl_up_sync(0xFFFFFFFFu, s, d);
            if (t >= d) s += x;
        }
        warp_sums[t] = s;
    }
    __syncthreads();
    unsigned warp_off = (t >= 32) ? warp_sums[(t >> 5) - 1] : 0u;
    unsigned base = warp_off + v - sum;   // exclusive over thread groups
    g_bprefix[t * 4 + 0] = base;
    g_bprefix[t * 4 + 1] = base + v0;
    g_bprefix[t * 4 + 2] = base + v0 + v1;
    g_bprefix[t * 4 + 3] = base + v0 + v1 + v2;
}

// ---------------------------------------------------------------------------
// Pass 3: partition points into bucket-grouped array (deterministic bases).
// ---------------------------------------------------------------------------
__global__ __launch_bounds__(1024) void k_partition(const float* __restrict__ feats, int n, int chunk) {
    __shared__ unsigned cnt[NBUCK];
    for (int i = threadIdx.x; i < NBUCK; i += 1024) cnt[i] = 0;
    __syncthreads();
    int c = blockIdx.x;
    int lo = c * chunk;
    int hi = min(n, lo + chunk);
    for (int i = lo + threadIdx.x; i < hi; i += 1024) {
        unsigned comb = g_combined[i];
        float f = feats[i];
        unsigned b = comb >> 15;            // key>>12
        unsigned local = atomicAdd(&cnt[b], 1u);
        unsigned pos = g_bprefix[b] + g_hist[c * NBUCK + b] + local;
        g_bucket[pos] = make_uint2(comb, __float_as_uint(f));
    }
}

// ---------------------------------------------------------------------------
// Pass 4: one block per bucket — accumulate rows in smem, emit full rows
// (coords float4 + feats 2x float4) with plain stores. No global atomics,
// no pre-zero of the output.
// ---------------------------------------------------------------------------
extern __shared__ unsigned s_dyn[];
__global__ __launch_bounds__(512) void k_scatter_rows(float4* __restrict__ out_coords,
                                                      float* __restrict__ out_feats) {
    float*    accum = (float*)s_dyn;                       // KPB*8 floats = 128KB
    unsigned* sbit  = (unsigned*)(s_dyn + KPB * 8);        // 128 words
    unsigned* spre  = sbit + WPB;                          // 128 words
    int b = blockIdx.x;
    for (int i = threadIdx.x; i < KPB * 8; i += 512) accum[i] = 0.f;
    if (threadIdx.x < WPB) {
        sbit[threadIdx.x] = g_bitmap[b * WPB + threadIdx.x];
        spre[threadIdx.x] = g_wprefix[b * WPB + threadIdx.x];
    }
    __syncthreads();
    unsigned lo = g_bprefix[b];
    unsigned hi = lo + g_btotal[b];
    for (unsigned i = lo + threadIdx.x; i < hi; i += 512) {
        uint2 e = g_bucket[i];
        unsigned local = (e.x >> 3) & (KPB - 1u);
        unsigned off   = e.x & 7u;
        atomicAdd(&accum[local * 8 + off], __uint_as_float(e.y));
    }
    __syncthreads();
    // all 128 words of this bucket share one 1024-word scan block: (b*128)>>10 == b>>3
    unsigned bsum = g_blocksums[b >> 3];
    unsigned keybase = (unsigned)b * KPB;
    for (int k = threadIdx.x; k < KPB; k += 512) {
        unsigned w = (unsigned)k >> 5, bit = (unsigned)k & 31u;
        unsigned word = sbit[w];
        if (!((word >> bit) & 1u)) continue;
        unsigned rank = spre[w] + bsum + (unsigned)__popc(word & ((1u << bit) - 1u));
        unsigned kk = keybase + (unsigned)k;
        out_coords[rank] = make_float4((float)(kk >> 24), (float)((kk >> 16) & 255u),
                                       (float)((kk >> 8) & 255u), (float)(kk & 255u));
        float4* fo = (float4*)(out_feats + (size_t)rank * 8u);
        float4* fa = (float4*)(accum + (size_t)k * 8u);
        fo[0] = fa[0];
        fo[1] = fa[1];
    }
}

// ---------------------------------------------------------------------------
// Pass 5: invalid tail rows: coords=-1, feats=0.
// ---------------------------------------------------------------------------
__global__ void k_fill_invalid(float4* __restrict__ out_coords,
                               float4* __restrict__ out_feats4, int n) {
    int i = blockIdx.x * blockDim.x + threadIdx.x;
    if (i >= n || (unsigned)i < g_total) return;
    out_coords[i] = make_float4(-1.f, -1.f, -1.f, -1.f);
    out_feats4[i * 2]     = make_float4(0.f, 0.f, 0.f, 0.f);
    out_feats4[i * 2 + 1] = make_float4(0.f, 0.f, 0.f, 0.f);
}

extern "C" void kernel_launch(void* const* d_in, const int* in_sizes, int n_in,
                              void* d_out, int out_size) {
    const int4*  coords = (const int4*)d_in[0];
    const float* feats  = (const float*)d_in[1];
    int n = in_sizes[0] / 4;
    int chunk = (n + NCHUNK - 1) / NCHUNK;

    float4* out_coords = (float4*)d_out;
    float*  out_feats  = (float*)((char*)d_out + (size_t)n * 4 * sizeof(float));

    const int DYNSMEM = KPB * 8 * (int)sizeof(float) + 2 * WPB * (int)sizeof(unsigned);
    cudaFuncSetAttribute(k_scatter_rows, cudaFuncAttributeMaxDynamicSharedMemorySize, DYNSMEM);

    k_zero_bitmap  <<<((NWORDS / 4) + 255) / 256, 256>>>();
    k_build        <<<NCHUNK, 1024>>>(coords, n, chunk);
    k_scan_words   <<<NBLKS, 1024>>>();
    k_scan_blocks  <<<1, NBLKS>>>();
    k_chunkpref    <<<NBUCK / 256, 256>>>();
    k_bucket_prefix<<<1, 1024>>>();
    k_partition    <<<NCHUNK, 1024>>>(feats, n, chunk);
    k_scatter_rows <<<NBUCK, 512, DYNSMEM>>>(out_coords, out_feats);
    k_fill_invalid <<<(n + 255) / 256, 256>>>(out_coords, (float4*)out_feats, n);
}

// round 8
// speedup vs baseline: 1.4741x; 1.4741x over previous
#include <cuda_runtime.h>
#include <cstdint>

// Problem constants: G=512, GP=256, keys fit in 24 bits since b==0.
#define NKEYS  (1u << 24)          // 16,777,216 possible parent keys
#define NWORDS (1u << 19)          // bitmap words (32 keys/word) = 524,288
#define NBLKS  (NWORDS / 1024)     // 512 scan blocks
#define NMAX   4000000

// Scratch (static device globals — no allocation allowed in kernel_launch)
__device__ unsigned g_bitmap[NWORDS];     // presence bitmap over key space
__device__ unsigned g_wprefix[NWORDS];    // per-word excl popcount prefix (within 1024-word block)
__device__ unsigned g_blocksums[NBLKS];   // per-block totals -> exclusive prefix
__device__ unsigned g_total;              // total number of unique keys
__device__ unsigned g_combined[NMAX];     // (key<<3)|offset per point

__global__ void k_zero_bitmap() {
    unsigned i = blockIdx.x * blockDim.x + threadIdx.x;
    if (i < NWORDS / 4) reinterpret_cast<uint4*>(g_bitmap)[i] = make_uint4(0, 0, 0, 0);
}

// ---------------------------------------------------------------------------
// Pass 1: per point, compute key + child-offset, mark presence bit.
// coords row = {b, x, y, z}; parent = xyz>>1; offset = (x&1)*4+(y&1)*2+(z&1)
// key = ((b*256 + px)*256 + py)*256 + pz   (< 2^24 since b==0)
// ---------------------------------------------------------------------------
__global__ void k_build(const int4* __restrict__ coords, int n) {
    int i = blockIdx.x * blockDim.x + threadIdx.x;
    if (i >= n) return;
    int4 c = coords[i];
    unsigned key = (((unsigned)c.x * 256u + (((unsigned)c.y) >> 1)) * 256u
                    + (((unsigned)c.z) >> 1)) * 256u + (((unsigned)c.w) >> 1);
    unsigned off = (((unsigned)c.y & 1u) << 2) | (((unsigned)c.z & 1u) << 1)
                 | ((unsigned)c.w & 1u);
    g_combined[i] = (key << 3) | off;
    atomicOr(&g_bitmap[key >> 5], 1u << (key & 31u));
}

// ---------------------------------------------------------------------------
// Pass 2a: per-block (1024 words) exclusive scan of bitmap popcounts.
// ---------------------------------------------------------------------------
__global__ void k_scan_words() {
    __shared__ unsigned warp_sums[32];
    unsigned w = blockIdx.x * 1024u + threadIdx.x;
    unsigned c = __popc(g_bitmap[w]);
    unsigned v = c;
    #pragma unroll
    for (int d = 1; d < 32; d <<= 1) {
        unsigned t = __shfl_up_sync(0xFFFFFFFFu, v, d);
        if ((threadIdx.x & 31u) >= (unsigned)d) v += t;
    }
    if ((threadIdx.x & 31u) == 31u) warp_sums[threadIdx.x >> 5] = v;
    __syncthreads();
    if (threadIdx.x < 32) {
        unsigned s = warp_sums[threadIdx.x];
        #pragma unroll
        for (int d = 1; d < 32; d <<= 1) {
            unsigned t = __shfl_up_sync(0xFFFFFFFFu, s, d);
            if (threadIdx.x >= (unsigned)d) s += t;
        }
        warp_sums[threadIdx.x] = s;
    }
    __syncthreads();
    unsigned warp_off = (threadIdx.x >= 32) ? warp_sums[(threadIdx.x >> 5) - 1] : 0u;
    g_wprefix[w] = warp_off + v - c;
    if (threadIdx.x == 1023) g_blocksums[blockIdx.x] = warp_off + v;
}

// ---------------------------------------------------------------------------
// Pass 2b: exclusive scan of 512 block totals; publish g_total.
// ---------------------------------------------------------------------------
__global__ void k_scan_blocks() {
    __shared__ unsigned warp_sums[16];
    unsigned c = g_blocksums[threadIdx.x];
    unsigned v = c;
    #pragma unroll
    for (int d = 1; d < 32; d <<= 1) {
        unsigned t = __shfl_up_sync(0xFFFFFFFFu, v, d);
        if ((threadIdx.x & 31u) >= (unsigned)d) v += t;
    }
    if ((threadIdx.x & 31u) == 31u) warp_sums[threadIdx.x >> 5] = v;
    __syncthreads();
    if (threadIdx.x < 16) {
        unsigned s = warp_sums[threadIdx.x];
        #pragma unroll
        for (int d = 1; d < 16; d <<= 1) {
            unsigned t = __shfl_up_sync(0xFFFFu, s, d);
            if (threadIdx.x >= (unsigned)d) s += t;
        }
        warp_sums[threadIdx.x] = s;
    }
    __syncthreads();
    unsigned warp_off = (threadIdx.x >= 32) ? warp_sums[(threadIdx.x >> 5) - 1] : 0u;
    g_blocksums[threadIdx.x] = warp_off + v - c;
    if (threadIdx.x == NBLKS - 1) g_total = warp_off + v;
}

// ---------------------------------------------------------------------------
// Pass 3 (per key half): emit sorted unique coords (float32) AND zero that
// row's feats slot. Rank-ordered writes; warms L2 for the scatter that follows.
// ---------------------------------------------------------------------------
__global__ void k_coords_half(float4* __restrict__ out_coords,
                              float4* __restrict__ out_feats4, unsigned keybase) {
    unsigned k = keybase + blockIdx.x * blockDim.x + threadIdx.x;
    unsigned w    = k >> 5;
    unsigned bit  = k & 31u;
    unsigned word = g_bitmap[w];
    if (!((word >> bit) & 1u)) return;
    unsigned rank = g_wprefix[w] + g_blocksums[w >> 10]
                  + (unsigned)__popc(word & ((1u << bit) - 1u));
    out_coords[rank] = make_float4((float)(k >> 24), (float)((k >> 16) & 255u),
                                   (float)((k >> 8) & 255u), (float)(k & 255u));
    out_feats4[(size_t)rank * 2]     = make_float4(0.f, 0.f, 0.f, 0.f);
    out_feats4[(size_t)rank * 2 + 1] = make_float4(0.f, 0.f, 0.f, 0.f);
}

// ---------------------------------------------------------------------------
// Pass 4 (per key half): rank + atomic add feature. Active region ~57MB,
// L2-resident (just warmed by k_coords_half of the same half).
// ---------------------------------------------------------------------------
__global__ void k_scatter_half(const float* __restrict__ feats,
                               float* __restrict__ out_feats, int n, unsigned half) {
    int i = blockIdx.x * blockDim.x + threadIdx.x;
    if (i >= n) return;
    unsigned comb = g_combined[i];
    unsigned key  = comb >> 3;
    if ((key >> 23) != half) return;
    unsigned off  = comb & 7u;
    unsigned w    = key >> 5;
    unsigned bit  = key & 31u;
    unsigned word = g_bitmap[w];
    unsigned rank = g_wprefix[w] + g_blocksums[w >> 10]
                  + (unsigned)__popc(word & ((1u << bit) - 1u));
    atomicAdd(&out_feats[(size_t)rank * 8u + off], feats[i]);
}

// ---------------------------------------------------------------------------
// Pass 5: invalid tail rows (rank >= g_total): coords=-1, feats=0.
// ---------------------------------------------------------------------------
__global__ void k_fill_invalid(float4* __restrict__ out_coords,
                               float4* __restrict__ out_feats4, int n) {
    int i = blockIdx.x * blockDim.x + threadIdx.x;
    if (i >= n || (unsigned)i < g_total) return;
    out_coords[i] = make_float4(-1.f, -1.f, -1.f, -1.f);
    out_feats4[(size_t)i * 2]     = make_float4(0.f, 0.f, 0.f, 0.f);
    out_feats4[(size_t)i * 2 + 1] = make_float4(0.f, 0.f, 0.f, 0.f);
}

extern "C" void kernel_launch(void* const* d_in, const int* in_sizes, int n_in,
                              void* d_out, int out_size) {
    const int4*  coords = (const int4*)d_in[0];
    const float* feats  = (const float*)d_in[1];
    int n = in_sizes[0] / 4;   // N points

    float4* out_coords = (float4*)d_out;
    float*  out_feats  = (float*)((char*)d_out + (size_t)n * 4 * sizeof(float));
    float4* out_feats4 = (float4*)out_feats;

    k_zero_bitmap <<<((NWORDS / 4) + 255) / 256, 256>>>();
    k_build       <<<(n + 255) / 256, 256>>>(coords, n);
    k_scan_words  <<<NBLKS, 1024>>>();
    k_scan_blocks <<<1, NBLKS>>>();
    // Half 0: zero+coords (warm L2), then scatter into it.
    k_coords_half <<<(1u << 23) / 256, 256>>>(out_coords, out_feats4, 0u);
    k_scatter_half<<<(n + 255) / 256, 256>>>(feats, out_feats, n, 0u);
    // Half 1.
    k_coords_half <<<(1u << 23) / 256, 256>>>(out_coords, out_feats4, 1u << 23);
    k_scatter_half<<<(n + 255) / 256, 256>>>(feats, out_feats, n, 1u);
    k_fill_invalid<<<(n + 255) / 256, 256>>>(out_coords, out_feats4, n);
}